// round 8
// baseline (speedup 1.0000x reference)
#include <cuda_runtime.h>
#include <cuda_bf16.h>
#include <math.h>
#include <stdint.h>

// Inter-layer scratch + sync (allocation-free rule: __device__ globals).
__device__ float g_out0[729];
__device__ float g_out1[27];
__device__ unsigned g_grp[27];   // per-layer1-chain producer counters (27 each)
__device__ unsigned g_ctr1;      // layer1 completion counter

#define PI_HALF 1.57079632679489662f
#define STAGE_FLOATS 2048

// ---------------- helpers ----------------
__device__ __forceinline__ float warp_sum(float v) {
#pragma unroll
    for (int o = 16; o > 0; o >>= 1)
        v += __shfl_down_sync(0xffffffffu, v, o);
    return v;
}
__device__ __forceinline__ void l2_prefetch_line(const float* p) {
    asm volatile("prefetch.global.L2 [%0];" :: "l"(p));
}
__device__ __forceinline__ void spin_until(const unsigned* c, unsigned target) {
    unsigned v;
    do {
        asm volatile("ld.global.acquire.gpu.u32 %0, [%1];"
                     : "=r"(v) : "l"(c) : "memory");
        if (v >= target) return;
        __nanosleep(128);
    } while (true);
}

// Load one 8 KB stage, column layout: buf[d] = A[d][0][t], buf[32+d] = A[d][1][t].
// 64 independent coalesced LDG.32 per lane; no barriers -> ptxas front-batches.
__device__ __forceinline__ void load_stage(float (&buf)[64],
                                           const float* __restrict__ g, int t) {
#pragma unroll
    for (int d = 0; d < 32; d++) {
        buf[d]      = __ldcs(g + d * 64 + t);
        buf[32 + d] = __ldcs(g + d * 64 + 32 + t);
    }
}
// Forward step: v_new[t] = sum_d v[d] * (A[d][0][t]*c + A[d][1][t]*s)
__device__ __forceinline__ float step_fwd(const float (&buf)[64], float v,
                                          float c, float s) {
    float acc = 0.0f;
#pragma unroll
    for (int d = 0; d < 32; d++) {
        const float vd = __shfl_sync(0xffffffffu, v, d);
        acc = fmaf(vd, fmaf(buf[d], c, buf[32 + d] * s), acc);
    }
    return acc;
}

// Full 25-stage scalar chain, register double-buffered, barrier-free.
__device__ __forceinline__ float chain_fwd(
    const float* __restrict__ mid, const float* __restrict__ first,
    const float* __restrict__ last, const float* sc, const float* ss, int t)
{
    float v = fmaf(first[t], sc[0], first[32 + t] * ss[0]);
    float A[64], B[64];
    const float* g = mid;
    load_stage(A, g, t);
#pragma unroll 1
    for (int it = 0; it < 12; it++) {
        load_stage(B, g + STAGE_FLOATS, t);           // stage 2it+1 in flight
        v = step_fwd(A, v, sc[2 * it + 1], ss[2 * it + 1]);   // stage 2it
        load_stage(A, g + 2 * STAGE_FLOATS, t);       // stage 2it+2 in flight
        v = step_fwd(B, v, sc[2 * it + 2], ss[2 * it + 2]);   // stage 2it+1
        g += 2 * STAGE_FLOATS;
    }
    v = step_fwd(A, v, sc[25], ss[25]);               // stage 24
    const float pv = v * fmaf(last[2 * t], sc[26], last[2 * t + 1] * ss[26]);
    return warp_sum(pv);
}

// Row load for the backward (final) chain: lane t reads its own contiguous
// 256-B row as 16 float4 (L2-resident data; wavefront cost irrelevant here).
__device__ __forceinline__ void load_row(float (&buf)[64],
                                         const float* __restrict__ g, int t) {
    const float4* __restrict__ r = (const float4*)(g + t * 64);
#pragma unroll
    for (int i = 0; i < 16; i++) {
        const float4 q = r[i];
        buf[4 * i + 0] = q.x; buf[4 * i + 1] = q.y;
        buf[4 * i + 2] = q.z; buf[4 * i + 3] = q.w;
    }
}
// Backward step: u_new[t] = c*(A[t][0][:]·u) + s*(A[t][1][:]·u)
__device__ __forceinline__ float step_bwd(const float (&buf)[64], float u,
                                          float c, float s) {
    float a0 = 0.0f, a1 = 0.0f;
#pragma unroll
    for (int e = 0; e < 32; e++) {
        const float ue = __shfl_sync(0xffffffffu, u, e);
        a0 = fmaf(buf[e], ue, a0);
        a1 = fmaf(buf[32 + e], ue, a1);
    }
    return fmaf(a0, c, a1 * s);
}

__global__ void reset_kernel() {
    if (threadIdx.x < 27) g_grp[threadIdx.x] = 0;
    if (threadIdx.x == 27) g_ctr1 = 0;
}

// Persistent fused kernel: 729 blocks x 32 threads, one wave.
// Blocks 0-26 additionally run layer 1; block 0 additionally runs the final layer.
__global__ void __launch_bounds__(32)
fused_kernel(const float* __restrict__ img,
             const float* __restrict__ l0f, const float* __restrict__ l0m,
             const float* __restrict__ l0l,
             const float* __restrict__ l1f, const float* __restrict__ l1m,
             const float* __restrict__ l1l,
             const float* __restrict__ ff,  const float* __restrict__ fm,
             const float* __restrict__ fl,
             float* __restrict__ out)
{
    __shared__ float sc[27], ss[27];

    const int n = blockIdx.x;
    const int t = threadIdx.x;

    // ---------- Layer 0 ----------
    if (t < 27) {
        const int bh = n / 81, bv = (n / 9) % 9, bd = n % 9;
        const int x = t / 9, y = (t / 3) % 3, z = t % 3;
        const float val = img[(3 * bh + x) * 729 + (3 * bv + y) * 27 + (3 * bd + z)];
        float cv, sv;
        sincosf(PI_HALF * val, &sv, &cv);
        sc[t] = cv; ss[t] = sv;
    }
    __syncwarp();

    const float* gm0 = l0m + (long)n * (25 * STAGE_FLOATS);
    float r = chain_fwd(gm0, l0f + n * 64, l0l + n * 64, sc, ss, t);
    if (t == 0) {
        g_out0[n] = r;
        __threadfence();
        const int X = n / 81, Y = (n / 9) % 9, Z = n % 9;
        atomicAdd(&g_grp[(X / 3) * 9 + (Y / 3) * 3 + (Z / 3)], 1u);
    }
    if (n >= 27) return;

    // ---------- Layer 1 (blocks 0..26) ----------
    const float* gm1 = l1m + n * (25 * STAGE_FLOATS);
    // L2-warm the weights BEFORE spinning so the chain runs from L2.
    for (int i = t; i < 25 * STAGE_FLOATS / 32; i += 32)
        l2_prefetch_line(gm1 + i * 32);
    if (n == 0) {
        for (int i = t; i < 25 * STAGE_FLOATS / 32; i += 32)
            l2_prefetch_line(fm + i * 32);
    }
    spin_until(&g_grp[n], 27u);

    __syncwarp();
    if (t < 27) {
        const int bh = n / 9, bv = (n / 3) % 3, bd = n % 3;
        const int x = t / 9, y = (t / 3) % 3, z = t % 3;
        const float val = __ldcg(&g_out0[(3 * bh + x) * 81 + (3 * bv + y) * 9 + (3 * bd + z)]);
        float cv, sv;
        sincosf(PI_HALF * val, &sv, &cv);
        sc[t] = cv; ss[t] = sv;
    }
    __syncwarp();

    r = chain_fwd(gm1, l1f + n * 64, l1l + n * 64, sc, ss, t);
    if (t == 0) {
        g_out1[n] = r;
        __threadfence();
        atomicAdd(&g_ctr1, 1u);
    }
    if (n != 0) return;

    // ---------- Final layer (block 0): right-to-left, output leg at the end ----------
    spin_until(&g_ctr1, 27u);

    __syncwarp();
    if (t < 27) {
        // (3,3,3) squeeze of g_out1 is the identity permutation
        float cv, sv;
        sincosf(PI_HALF * __ldcg(&g_out1[t]), &sv, &cv);
        sc[t] = cv; ss[t] = sv;
    }
    __syncwarp();

    // u_25[d] = last[d,0]*c26 + last[d,1]*s26
    float u = fmaf(fl[2 * t], sc[26], fl[2 * t + 1] * ss[26]);

    float A[64], B[64];
    load_row(A, fm + 24 * STAGE_FLOATS, t);
#pragma unroll 1
    for (int it = 0; it < 12; it++) {
        const int st = 24 - 2 * it;                  // A holds stage st
        load_row(B, fm + (st - 1) * STAGE_FLOATS, t);
        u = step_bwd(A, u, sc[st + 1], ss[st + 1]);
        load_row(A, fm + (st - 2) * STAGE_FLOATS, t);
        u = step_bwd(B, u, sc[st], ss[st]);
    }
    u = step_bwd(A, u, sc[1], ss[1]);                // stage 0

#pragma unroll
    for (int o = 0; o < 10; o++) {
        float p = fmaf(ff[o * 32 + t], sc[0], ff[320 + o * 32 + t] * ss[0]) * u;
        p = warp_sum(p);
        if (t == 0) out[o] = p;
    }
}

extern "C" void kernel_launch(void* const* d_in, const int* in_sizes, int n_in,
                              void* d_out, int out_size)
{
    const float* img      = (const float*)d_in[0];
    const float* l0_first = (const float*)d_in[1];
    const float* l0_mid   = (const float*)d_in[2];
    const float* l0_last  = (const float*)d_in[3];
    const float* l1_first = (const float*)d_in[4];
    const float* l1_mid   = (const float*)d_in[5];
    const float* l1_last  = (const float*)d_in[6];
    const float* f_first  = (const float*)d_in[7];
    const float* f_mid    = (const float*)d_in[8];
    const float* f_last   = (const float*)d_in[9];
    float* out = (float*)d_out;

    reset_kernel<<<1, 32>>>();
    fused_kernel<<<729, 32>>>(img, l0_first, l0_mid, l0_last,
                              l1_first, l1_mid, l1_last,
                              f_first, f_mid, f_last, out);
}